// round 4
// baseline (speedup 1.0000x reference)
#include <cuda_runtime.h>
#include <cuda_fp16.h>
#include <cstdint>

#define MAX_ENT   50000
#define MAX_E     1600000
#define MAX_REL   10       // N_REL - 1
#define C_DIM     128
#define C_VEC     (C_DIM / 4)    // 32 float4 per fp32 row
#define C_U4V     (C_DIM / 8)    // 16 uint4 (8 halves) per fp16 row

// ---------------- device scratch (static globals: no allocation allowed) ----
__device__ int            g_is64;
__device__ int            g_head[MAX_E];
__device__ unsigned short g_rank[MAX_E];     // within-head slot from histogram
__device__ unsigned       g_val[MAX_E];      // packed tail | (rel<<20)
__device__ unsigned       g_csr[MAX_E];      // CSR values: packed tail|rel
__device__ int            g_cnt[MAX_ENT];
__device__ int            g_row_start[MAX_ENT + 1];
__device__ uint4          g_embH[MAX_ENT * C_U4V];  // fp16 input embeddings
__device__ uint4          g_embA[MAX_ENT * C_U4V];  // fp16 hop-1 output
__device__ uint4          g_embB[MAX_ENT * C_U4V];  // fp16 hop-2 output
__device__ uint4          g_embC[MAX_ENT * C_U4V];  // fp16 hop-3 output

// ---------------------------------------------------------------------------
// 0) zero per-head counters + int64/int32 width detection (int64 ids < 2^31
//    have all odd 32-bit words zero; statistically impossible for the int32
//    interpretation of random ids in [0,50000)).
__global__ void init_detect_kernel(const unsigned* __restrict__ words, int n_ent) {
    int i = blockIdx.x * blockDim.x + threadIdx.x;
    if (i < n_ent) g_cnt[i] = 0;
    if (i == 0) {
        int is64 = 1;
        #pragma unroll 1
        for (int k = 1; k < 256; k += 2) {
            if (words[k] != 0u) { is64 = 0; break; }
        }
        g_is64 = is64;
    }
}

// 1) decode edges, histogram head degrees, record within-head rank
__global__ void build_a_kernel(const void* __restrict__ edge_index,
                               const void* __restrict__ edge_type, int E) {
    int j = blockIdx.x * blockDim.x + threadIdx.x;
    if (j >= E) return;
    int head, tail, rel;
    if (g_is64) {
        const long long* ei = (const long long*)edge_index;
        const long long* et = (const long long*)edge_type;
        head = (int)ei[j];
        tail = (int)ei[E + j];
        rel  = (int)et[j] - 1;
    } else {
        const int* ei = (const int*)edge_index;
        const int* et = (const int*)edge_type;
        head = ei[j];
        tail = ei[E + j];
        rel  = et[j] - 1;
    }
    g_head[j] = head;
    g_val[j]  = (unsigned)tail | ((unsigned)rel << 20);
    int r = atomicAdd(&g_cnt[head], 1);
    g_rank[j] = (unsigned short)r;           // degrees ~Poisson(32) << 65536
}

// 2) exclusive scan of g_cnt -> g_row_start.  Single block, 1024 threads.
__global__ void scan_kernel(int n_ent) {
    __shared__ int ssum[1024];
    const int t    = threadIdx.x;
    const int PER  = (n_ent + 1023) / 1024;
    const int base = t * PER;

    int s = 0;
    for (int i = 0; i < PER; i++) {
        int idx = base + i;
        if (idx < n_ent) s += g_cnt[idx];
    }
    ssum[t] = s;
    __syncthreads();
    for (int off = 1; off < 1024; off <<= 1) {
        int v = (t >= off) ? ssum[t - off] : 0;
        __syncthreads();
        ssum[t] += v;
        __syncthreads();
    }
    int run = ssum[t] - s;
    for (int i = 0; i < PER; i++) {
        int idx = base + i;
        if (idx < n_ent) {
            g_row_start[idx] = run;
            run += g_cnt[idx];
        }
    }
    if (t == 1023) g_row_start[n_ent] = ssum[1023];
}

// 3) fill CSR values -- atomic-free: pos = row_start[head] + rank
__global__ void build_b_kernel(int E) {
    int j = blockIdx.x * blockDim.x + threadIdx.x;
    if (j >= E) return;
    int pos = g_row_start[g_head[j]] + (int)g_rank[j];
    g_csr[pos] = g_val[j];
}

// 4) convert entity_emb (fp32) -> fp16 table g_embH  (uint2 view, 4 ch/thread)
__global__ void convert_kernel(const float4* __restrict__ emb, int n_vec) {
    int i = blockIdx.x * blockDim.x + threadIdx.x;
    if (i >= n_vec) return;
    float4 f = emb[i];
    __half2 a = __floats2half2_rn(f.x, f.y);
    __half2 b = __floats2half2_rn(f.z, f.w);
    uint2 q;
    q.x = *(unsigned*)&a;
    q.y = *(unsigned*)&b;
    ((uint2*)g_embH)[i] = q;
}

// 5) fused hop: fp16 gather + relation scale + mean + L2-normalize + fp16
//    write.  16 lanes per entity (2 entities per warp); lane g covers
//    channels [8g, 8g+8).
__global__ __launch_bounds__(256)
void hop_kernel(const float4* __restrict__ weight,
                int n_ent, int n_rel, int hop) {
    __shared__ float4 sw[MAX_REL * C_VEC];   // 5 KB: all relation rows fp32
    for (int i = threadIdx.x; i < n_rel * C_VEC; i += blockDim.x)
        sw[i] = weight[i];
    __syncthreads();

    const uint4* src;
    uint4* dst;
    if (hop == 0)      { src = (const uint4*)g_embH; dst = (uint4*)g_embA; }
    else if (hop == 1) { src = (const uint4*)g_embA; dst = (uint4*)g_embB; }
    else               { src = (const uint4*)g_embB; dst = (uint4*)g_embC; }

    int tid = blockIdx.x * blockDim.x + threadIdx.x;
    int grp = tid >> 4;               // entity id
    int g   = threadIdx.x & 15;       // lane within 16-group
    if (grp >= n_ent) return;

    const int start = g_row_start[grp];
    const int end   = g_row_start[grp + 1];

    float acc[8];
    #pragma unroll
    for (int i = 0; i < 8; i++) acc[i] = 0.f;

    int k = start;
    // 8-wide unroll: 8 independent 128-bit gathers in flight per lane
    for (; k + 7 < end; k += 8) {
        unsigned v[8];
        uint4 p[8];
        #pragma unroll
        for (int u = 0; u < 8; u++) v[u] = g_csr[k + u];
        #pragma unroll
        for (int u = 0; u < 8; u++)
            p[u] = __ldg(&src[(v[u] & 0xFFFFFu) * C_U4V + g]);
        #pragma unroll
        for (int u = 0; u < 8; u++) {
            int wb = (int)(v[u] >> 20) * C_VEC + 2 * g;
            float4 wa = sw[wb];
            float4 wc = sw[wb + 1];
            float2 f0 = __half22float2(*(__half2*)&p[u].x);
            float2 f1 = __half22float2(*(__half2*)&p[u].y);
            float2 f2 = __half22float2(*(__half2*)&p[u].z);
            float2 f3 = __half22float2(*(__half2*)&p[u].w);
            acc[0] += f0.x * wa.x; acc[1] += f0.y * wa.y;
            acc[2] += f1.x * wa.z; acc[3] += f1.y * wa.w;
            acc[4] += f2.x * wc.x; acc[5] += f2.y * wc.y;
            acc[6] += f3.x * wc.z; acc[7] += f3.y * wc.w;
        }
    }
    for (; k < end; k++) {
        unsigned v = g_csr[k];
        uint4 p = __ldg(&src[(v & 0xFFFFFu) * C_U4V + g]);
        int wb = (int)(v >> 20) * C_VEC + 2 * g;
        float4 wa = sw[wb];
        float4 wc = sw[wb + 1];
        float2 f0 = __half22float2(*(__half2*)&p.x);
        float2 f1 = __half22float2(*(__half2*)&p.y);
        float2 f2 = __half22float2(*(__half2*)&p.z);
        float2 f3 = __half22float2(*(__half2*)&p.w);
        acc[0] += f0.x * wa.x; acc[1] += f0.y * wa.y;
        acc[2] += f1.x * wa.z; acc[3] += f1.y * wa.w;
        acc[4] += f2.x * wc.x; acc[5] += f2.y * wc.y;
        acc[6] += f3.x * wc.z; acc[7] += f3.y * wc.w;
    }

    // scatter_mean
    float inv = 1.0f / fmaxf((float)(end - start), 1.0f);
    #pragma unroll
    for (int i = 0; i < 8; i++) acc[i] *= inv;

    // L2 norm across 128 channels (8 per lane, 16 lanes)
    float ss = 0.f;
    #pragma unroll
    for (int i = 0; i < 8; i++) ss += acc[i] * acc[i];
    #pragma unroll
    for (int off = 8; off > 0; off >>= 1)
        ss += __shfl_xor_sync(0xFFFFFFFFu, ss, off);
    float scale = 1.0f / fmaxf(sqrtf(ss), 1e-12f);

    __half2 h0 = __floats2half2_rn(acc[0] * scale, acc[1] * scale);
    __half2 h1 = __floats2half2_rn(acc[2] * scale, acc[3] * scale);
    __half2 h2 = __floats2half2_rn(acc[4] * scale, acc[5] * scale);
    __half2 h3 = __floats2half2_rn(acc[6] * scale, acc[7] * scale);
    uint4 q;
    q.x = *(unsigned*)&h0;
    q.y = *(unsigned*)&h1;
    q.z = *(unsigned*)&h2;
    q.w = *(unsigned*)&h3;
    dst[grp * C_U4V + g] = q;
}

// 6) res = entity_emb + h1 + h2 + h3   (single streaming pass)
__global__ void finish_kernel(const float4* __restrict__ emb,
                              float4* __restrict__ res, int n_vec) {
    int i = blockIdx.x * blockDim.x + threadIdx.x;
    if (i >= n_vec) return;
    float4 r = emb[i];
    uint2 a = ((const uint2*)g_embA)[i];
    uint2 b = ((const uint2*)g_embB)[i];
    uint2 c = ((const uint2*)g_embC)[i];
    float2 ax = __half22float2(*(__half2*)&a.x), ay = __half22float2(*(__half2*)&a.y);
    float2 bx = __half22float2(*(__half2*)&b.x), by = __half22float2(*(__half2*)&b.y);
    float2 cx = __half22float2(*(__half2*)&c.x), cy = __half22float2(*(__half2*)&c.y);
    r.x += ax.x + bx.x + cx.x;
    r.y += ax.y + bx.y + cx.y;
    r.z += ay.x + by.x + cy.x;
    r.w += ay.y + by.y + cy.y;
    res[i] = r;
}

// ---------------------------------------------------------------------------
extern "C" void kernel_launch(void* const* d_in, const int* in_sizes, int n_in,
                              void* d_out, int out_size) {
    const float*  entity_emb = (const float*)d_in[0];
    const void*   edge_index = d_in[1];
    const void*   edge_type  = d_in[2];
    const float*  weight     = (const float*)d_in[3];

    const int n_ent = in_sizes[0] / C_DIM;     // 50000
    const int E     = in_sizes[2];             // 1600000
    const int n_rel = in_sizes[3] / C_DIM;     // 10

    const int TB = 256;
    const int n_vec = n_ent * C_VEC;

    // CSR build (once per launch; reused across the 3 hops)
    init_detect_kernel<<<(n_ent + TB - 1) / TB, TB>>>((const unsigned*)edge_index, n_ent);
    build_a_kernel<<<(E + TB - 1) / TB, TB>>>(edge_index, edge_type, E);
    scan_kernel<<<1, 1024>>>(n_ent);
    build_b_kernel<<<(E + TB - 1) / TB, TB>>>(E);
    convert_kernel<<<(n_vec + TB - 1) / TB, TB>>>((const float4*)entity_emb, n_vec);

    // 3 fused hops, 16 lanes per entity (16 entities per 256-thread block)
    const int hop_blocks = (n_ent * 16 + TB - 1) / TB;
    hop_kernel<<<hop_blocks, TB>>>((const float4*)weight, n_ent, n_rel, 0);
    hop_kernel<<<hop_blocks, TB>>>((const float4*)weight, n_ent, n_rel, 1);
    hop_kernel<<<hop_blocks, TB>>>((const float4*)weight, n_ent, n_rel, 2);

    // final accumulation into d_out
    finish_kernel<<<(n_vec + TB - 1) / TB, TB>>>(
        (const float4*)entity_emb, (float4*)d_out, n_vec);
}

// round 5
// speedup vs baseline: 1.2542x; 1.2542x over previous
#include <cuda_runtime.h>
#include <cuda_fp16.h>
#include <cstdint>

#define MAX_ENT   50000
#define MAX_E     1600000
#define MAX_REL   10       // N_REL - 1
#define C_DIM     128
#define C_VEC     (C_DIM / 4)    // 32 float4 per fp32 row
#define C_H2V     (C_DIM / 4)    // 32 uint2 (4 halves) per fp16 row

// ---------------- device scratch (static globals: no allocation allowed) ----
__device__ int            g_is64;
__device__ int            g_head[MAX_E];
__device__ unsigned short g_rank[MAX_E];     // within-head slot from histogram
__device__ unsigned       g_val[MAX_E];      // packed tail | (rel<<20)
__device__ unsigned       g_csr[MAX_E];      // CSR values: packed tail|rel
__device__ int            g_cnt[MAX_ENT];
__device__ int            g_row_start[MAX_ENT + 1];
__device__ uint2          g_embH[MAX_ENT * C_H2V];  // fp16 input embeddings
__device__ uint2          g_embA[MAX_ENT * C_H2V];  // fp16 hop-1 output
__device__ uint2          g_embB[MAX_ENT * C_H2V];  // fp16 hop-2 output
__device__ uint2          g_embC[MAX_ENT * C_H2V];  // fp16 hop-3 output

// ---------------------------------------------------------------------------
// 0) zero per-head counters + int64/int32 width detection (int64 ids < 2^31
//    have all odd 32-bit words zero; statistically impossible for the int32
//    interpretation of random ids in [0,50000)).
__global__ void init_detect_kernel(const unsigned* __restrict__ words, int n_ent) {
    int i = blockIdx.x * blockDim.x + threadIdx.x;
    if (i < n_ent) g_cnt[i] = 0;
    if (i == 0) {
        int is64 = 1;
        #pragma unroll 1
        for (int k = 1; k < 256; k += 2) {
            if (words[k] != 0u) { is64 = 0; break; }
        }
        g_is64 = is64;
    }
}

// 1) decode edges, histogram head degrees, record within-head rank
__global__ void build_a_kernel(const void* __restrict__ edge_index,
                               const void* __restrict__ edge_type, int E) {
    int j = blockIdx.x * blockDim.x + threadIdx.x;
    if (j >= E) return;
    int head, tail, rel;
    if (g_is64) {
        const long long* ei = (const long long*)edge_index;
        const long long* et = (const long long*)edge_type;
        head = (int)ei[j];
        tail = (int)ei[E + j];
        rel  = (int)et[j] - 1;
    } else {
        const int* ei = (const int*)edge_index;
        const int* et = (const int*)edge_type;
        head = ei[j];
        tail = ei[E + j];
        rel  = et[j] - 1;
    }
    g_head[j] = head;
    g_val[j]  = (unsigned)tail | ((unsigned)rel << 20);
    int r = atomicAdd(&g_cnt[head], 1);
    g_rank[j] = (unsigned short)r;           // degrees ~Poisson(32) << 65536
}

// 2) exclusive scan of g_cnt -> g_row_start.  Single block, 1024 threads.
__global__ void scan_kernel(int n_ent) {
    __shared__ int ssum[1024];
    const int t    = threadIdx.x;
    const int PER  = (n_ent + 1023) / 1024;
    const int base = t * PER;

    int s = 0;
    for (int i = 0; i < PER; i++) {
        int idx = base + i;
        if (idx < n_ent) s += g_cnt[idx];
    }
    ssum[t] = s;
    __syncthreads();
    for (int off = 1; off < 1024; off <<= 1) {
        int v = (t >= off) ? ssum[t - off] : 0;
        __syncthreads();
        ssum[t] += v;
        __syncthreads();
    }
    int run = ssum[t] - s;
    for (int i = 0; i < PER; i++) {
        int idx = base + i;
        if (idx < n_ent) {
            g_row_start[idx] = run;
            run += g_cnt[idx];
        }
    }
    if (t == 1023) g_row_start[n_ent] = ssum[1023];
}

// 3) fill CSR values -- atomic-free: pos = row_start[head] + rank
__global__ void build_b_kernel(int E) {
    int j = blockIdx.x * blockDim.x + threadIdx.x;
    if (j >= E) return;
    int pos = g_row_start[g_head[j]] + (int)g_rank[j];
    g_csr[pos] = g_val[j];
}

// 4) convert entity_emb (fp32) -> fp16 table g_embH
__global__ void convert_kernel(const float4* __restrict__ emb, int n_vec) {
    int i = blockIdx.x * blockDim.x + threadIdx.x;
    if (i >= n_vec) return;
    float4 f = emb[i];
    __half2 a = __floats2half2_rn(f.x, f.y);
    __half2 b = __floats2half2_rn(f.z, f.w);
    uint2 q;
    q.x = *(unsigned*)&a;
    q.y = *(unsigned*)&b;
    g_embH[i] = q;
}

// 5) fused hop: fp16 gather + relation scale + mean + L2-normalize + fp16
//    write.  One warp per entity (R3 layout: 32 lanes x uint2, 8-wide unroll).
__global__ __launch_bounds__(256)
void hop_kernel(const float4* __restrict__ weight,
                int n_ent, int n_rel, int hop) {
    __shared__ float4 sw[MAX_REL * C_VEC];   // 5 KB: all relation rows fp32
    for (int i = threadIdx.x; i < n_rel * C_VEC; i += blockDim.x)
        sw[i] = weight[i];
    __syncthreads();

    const uint2* src;
    uint2* dst;
    if (hop == 0)      { src = (const uint2*)g_embH; dst = (uint2*)g_embA; }
    else if (hop == 1) { src = (const uint2*)g_embA; dst = (uint2*)g_embB; }
    else               { src = (const uint2*)g_embB; dst = (uint2*)g_embC; }

    int warp = (blockIdx.x * blockDim.x + threadIdx.x) >> 5;
    int lane = threadIdx.x & 31;
    if (warp >= n_ent) return;

    const int start = g_row_start[warp];
    const int end   = g_row_start[warp + 1];

    float4 acc = make_float4(0.f, 0.f, 0.f, 0.f);

    int k = start;
    // 8-wide unroll: 8 independent 64-bit gathers in flight per lane
    for (; k + 7 < end; k += 8) {
        unsigned v[8];
        uint2 p[8];
        #pragma unroll
        for (int u = 0; u < 8; u++) v[u] = g_csr[k + u];
        #pragma unroll
        for (int u = 0; u < 8; u++)
            p[u] = src[(v[u] & 0xFFFFFu) * C_H2V + lane];
        #pragma unroll
        for (int u = 0; u < 8; u++) {
            float4 w = sw[(v[u] >> 20) * C_VEC + lane];
            float2 fa = __half22float2(*(__half2*)&p[u].x);
            float2 fb = __half22float2(*(__half2*)&p[u].y);
            acc.x += fa.x * w.x; acc.y += fa.y * w.y;
            acc.z += fb.x * w.z; acc.w += fb.y * w.w;
        }
    }
    for (; k < end; k++) {
        unsigned v = g_csr[k];
        uint2 p = src[(v & 0xFFFFFu) * C_H2V + lane];
        float4 w = sw[(v >> 20) * C_VEC + lane];
        float2 fa = __half22float2(*(__half2*)&p.x);
        float2 fb = __half22float2(*(__half2*)&p.y);
        acc.x += fa.x * w.x; acc.y += fa.y * w.y;
        acc.z += fb.x * w.z; acc.w += fb.y * w.w;
    }

    // scatter_mean
    float inv = 1.0f / fmaxf((float)(end - start), 1.0f);
    acc.x *= inv; acc.y *= inv; acc.z *= inv; acc.w *= inv;

    // L2 norm across 128 channels
    float ss = acc.x * acc.x + acc.y * acc.y + acc.z * acc.z + acc.w * acc.w;
    #pragma unroll
    for (int off = 16; off > 0; off >>= 1)
        ss += __shfl_xor_sync(0xFFFFFFFFu, ss, off);
    float scale = 1.0f / fmaxf(sqrtf(ss), 1e-12f);

    __half2 ha = __floats2half2_rn(acc.x * scale, acc.y * scale);
    __half2 hb = __floats2half2_rn(acc.z * scale, acc.w * scale);
    uint2 q;
    q.x = *(unsigned*)&ha;
    q.y = *(unsigned*)&hb;
    dst[warp * C_H2V + lane] = q;
}

// 6) res = entity_emb + h1 + h2 + h3   (single streaming pass)
__global__ void finish_kernel(const float4* __restrict__ emb,
                              float4* __restrict__ res, int n_vec) {
    int i = blockIdx.x * blockDim.x + threadIdx.x;
    if (i >= n_vec) return;
    float4 r = emb[i];
    uint2 a = g_embA[i];
    uint2 b = g_embB[i];
    uint2 c = g_embC[i];
    float2 ax = __half22float2(*(__half2*)&a.x), ay = __half22float2(*(__half2*)&a.y);
    float2 bx = __half22float2(*(__half2*)&b.x), by = __half22float2(*(__half2*)&b.y);
    float2 cx = __half22float2(*(__half2*)&c.x), cy = __half22float2(*(__half2*)&c.y);
    r.x += ax.x + bx.x + cx.x;
    r.y += ax.y + bx.y + cx.y;
    r.z += ay.x + by.x + cy.x;
    r.w += ay.y + by.y + cy.y;
    res[i] = r;
}

// ---------------------------------------------------------------------------
extern "C" void kernel_launch(void* const* d_in, const int* in_sizes, int n_in,
                              void* d_out, int out_size) {
    const float*  entity_emb = (const float*)d_in[0];
    const void*   edge_index = d_in[1];
    const void*   edge_type  = d_in[2];
    const float*  weight     = (const float*)d_in[3];

    const int n_ent = in_sizes[0] / C_DIM;     // 50000
    const int E     = in_sizes[2];             // 1600000
    const int n_rel = in_sizes[3] / C_DIM;     // 10

    const int TB = 256;
    const int n_vec = n_ent * C_VEC;

    // CSR build (once per launch; reused across the 3 hops)
    init_detect_kernel<<<(n_ent + TB - 1) / TB, TB>>>((const unsigned*)edge_index, n_ent);
    build_a_kernel<<<(E + TB - 1) / TB, TB>>>(edge_index, edge_type, E);
    scan_kernel<<<1, 1024>>>(n_ent);
    build_b_kernel<<<(E + TB - 1) / TB, TB>>>(E);
    convert_kernel<<<(n_vec + TB - 1) / TB, TB>>>((const float4*)entity_emb, n_vec);

    // 3 fused hops, one warp per entity (8 warps/block)
    const int hop_blocks = (n_ent * 32 + TB - 1) / TB;
    hop_kernel<<<hop_blocks, TB>>>((const float4*)weight, n_ent, n_rel, 0);
    hop_kernel<<<hop_blocks, TB>>>((const float4*)weight, n_ent, n_rel, 1);
    hop_kernel<<<hop_blocks, TB>>>((const float4*)weight, n_ent, n_rel, 2);

    // final accumulation into d_out
    finish_kernel<<<(n_vec + TB - 1) / TB, TB>>>(
        (const float4*)entity_emb, (float4*)d_out, n_vec);
}